// round 1
// baseline (speedup 1.0000x reference)
#include <cuda_runtime.h>

#define NN 50000
#define EE 800000
#define IN_F 128
#define HID 64
#define OUT_F 40
#define NLAYER 3

// ---- scratch (device globals: no allocation allowed) ----
__device__ float g_h[NN * HID];
__device__ float g_hw[NN * HID];
__device__ float g_r[NN * HID];
__device__ float g_dinv[NN];
__device__ int   g_cnt[NN];
__device__ int   g_rowptr[NN + 1];
__device__ int   g_fill[NN];
__device__ int   g_srcbuf[EE];

// ------------------------------------------------------------------
// CSR build
// ------------------------------------------------------------------
__global__ void zero_cnt_k() {
    int i = blockIdx.x * 256 + threadIdx.x;
    if (i < NN) g_cnt[i] = 0;
}

__global__ void count_deg_k(const int* __restrict__ ei) {
    int e = blockIdx.x * 256 + threadIdx.x;
    if (e < EE) atomicAdd(&g_cnt[ei[EE + e]], 1);
}

__global__ void dinv_k() {
    int i = blockIdx.x * 256 + threadIdx.x;
    if (i < NN) g_dinv[i] = rsqrtf((float)g_cnt[i] + 1.0f);
}

// single-block exclusive scan of g_cnt -> g_rowptr / g_fill
__global__ void scan_k() {
    __shared__ int sh[1024];
    __shared__ int carry;
    int tid = threadIdx.x;
    if (tid == 0) carry = 0;
    __syncthreads();
    for (int base = 0; base < NN; base += 1024) {
        int i = base + tid;
        int v = (i < NN) ? g_cnt[i] : 0;
        sh[tid] = v;
        __syncthreads();
        for (int off = 1; off < 1024; off <<= 1) {
            int t = (tid >= off) ? sh[tid - off] : 0;
            __syncthreads();
            sh[tid] += t;
            __syncthreads();
        }
        if (i < NN) {
            int ex = carry + sh[tid] - v;
            g_rowptr[i] = ex;
            g_fill[i]   = ex;
        }
        __syncthreads();
        if (tid == 1023) carry += sh[1023];
        __syncthreads();
    }
    if (tid == 0) g_rowptr[NN] = carry;
}

__global__ void fill_k(const int* __restrict__ ei) {
    int e = blockIdx.x * 256 + threadIdx.x;
    if (e < EE) {
        int s = ei[e];
        int d = ei[EE + e];
        int pos = atomicAdd(&g_fill[d], 1);
        g_srcbuf[pos] = s;
    }
}

// ------------------------------------------------------------------
// former1: h = x @ Wf + bf     [N,128] @ [128,64]
// blockDim (16,16): 64 cols in 4-col groups, 64 rows/block (4 rows/thread)
// ------------------------------------------------------------------
__global__ void former1_k(const float* __restrict__ x,
                          const float* __restrict__ Wf,
                          const float* __restrict__ bf) {
    __shared__ float Ws[IN_F][HID];
    __shared__ float bs[HID];
    int tid = threadIdx.y * 16 + threadIdx.x;
    for (int idx = tid; idx < IN_F * HID; idx += 256)
        Ws[idx >> 6][idx & 63] = Wf[idx];
    if (tid < HID) bs[tid] = bf[tid];
    __syncthreads();

    int c0   = threadIdx.x * 4;
    int row0 = blockIdx.x * 64 + threadIdx.y * 4;
    int r[4];
#pragma unroll
    for (int rr = 0; rr < 4; rr++) r[rr] = min(row0 + rr, NN - 1);

    float acc[4][4] = {};
#pragma unroll 4
    for (int k = 0; k < IN_F; k++) {
        float4 w = *(const float4*)&Ws[k][c0];
#pragma unroll
        for (int rr = 0; rr < 4; rr++) {
            float xv = x[r[rr] * IN_F + k];
            acc[rr][0] += xv * w.x;
            acc[rr][1] += xv * w.y;
            acc[rr][2] += xv * w.z;
            acc[rr][3] += xv * w.w;
        }
    }
#pragma unroll
    for (int rr = 0; rr < 4; rr++) {
        int row = row0 + rr;
        if (row < NN) {
            float4 v = make_float4(acc[rr][0] + bs[c0],
                                   acc[rr][1] + bs[c0 + 1],
                                   acc[rr][2] + bs[c0 + 2],
                                   acc[rr][3] + bs[c0 + 3]);
            *(float4*)&g_h[row * HID + c0] = v;
        }
    }
}

// ------------------------------------------------------------------
// per-layer fused GEMM pair: hw = h@convW ; r = h@linW + linB + convB
// blockDim (32,8): 128 combined cols in 4-col groups, 32 rows/block
// ------------------------------------------------------------------
__global__ void layer_gemm_k(const float* __restrict__ convW,
                             const float* __restrict__ convB,
                             const float* __restrict__ linW,
                             const float* __restrict__ linB) {
    __shared__ float Ws[HID][128];
    __shared__ float bs[HID];
    int tid = threadIdx.y * 32 + threadIdx.x;
    for (int idx = tid; idx < HID * 128; idx += 256) {
        int k = idx >> 7, j = idx & 127;
        Ws[k][j] = (j < 64) ? convW[k * 64 + j] : linW[k * 64 + j - 64];
    }
    if (tid < HID) bs[tid] = convB[tid] + linB[tid];
    __syncthreads();

    int c0   = threadIdx.x * 4;                 // combined col [0,128)
    int row0 = blockIdx.x * 32 + threadIdx.y * 4;
    int r[4];
#pragma unroll
    for (int rr = 0; rr < 4; rr++) r[rr] = min(row0 + rr, NN - 1);

    float acc[4][4] = {};
#pragma unroll 4
    for (int k = 0; k < HID; k++) {
        float4 w = *(const float4*)&Ws[k][c0];
#pragma unroll
        for (int rr = 0; rr < 4; rr++) {
            float xv = g_h[r[rr] * HID + k];
            acc[rr][0] += xv * w.x;
            acc[rr][1] += xv * w.y;
            acc[rr][2] += xv * w.z;
            acc[rr][3] += xv * w.w;
        }
    }
    bool isR = (c0 >= 64);
    int  cc  = isR ? (c0 - 64) : c0;
#pragma unroll
    for (int rr = 0; rr < 4; rr++) {
        int row = row0 + rr;
        if (row < NN) {
            float4 v = make_float4(acc[rr][0], acc[rr][1], acc[rr][2], acc[rr][3]);
            if (isR) {
                v.x += bs[cc]; v.y += bs[cc + 1];
                v.z += bs[cc + 2]; v.w += bs[cc + 3];
                *(float4*)&g_r[row * HID + cc] = v;
            } else {
                *(float4*)&g_hw[row * HID + cc] = v;
            }
        }
    }
}

// ------------------------------------------------------------------
// aggregation + self loop + residual + BN(eval) + ReLU  (warp per node)
// ------------------------------------------------------------------
__global__ void agg_k(const float* __restrict__ gamma,
                      const float* __restrict__ beta,
                      const float* __restrict__ mean,
                      const float* __restrict__ var) {
    int warp = threadIdx.x >> 5;
    int lane = threadIdx.x & 31;
    int node = blockIdx.x * 8 + warp;
    if (node >= NN) return;

    float dn   = g_dinv[node];
    float self = dn * dn;
    int beg = g_rowptr[node], end = g_rowptr[node + 1];

    float a0 = g_hw[node * 64 + lane] * self;
    float a1 = g_hw[node * 64 + 32 + lane] * self;
    for (int i = beg; i < end; i++) {
        int   s = g_srcbuf[i];
        float c = g_dinv[s] * dn;
        a0 += c * g_hw[s * 64 + lane];
        a1 += c * g_hw[s * 64 + 32 + lane];
    }
    a0 += g_r[node * 64 + lane];
    a1 += g_r[node * 64 + 32 + lane];

    float s0 = gamma[lane]      * rsqrtf(var[lane]      + 1e-5f);
    float s1 = gamma[32 + lane] * rsqrtf(var[32 + lane] + 1e-5f);
    g_h[node * 64 + lane]      = fmaxf((a0 - mean[lane])      * s0 + beta[lane],      0.f);
    g_h[node * 64 + 32 + lane] = fmaxf((a1 - mean[32 + lane]) * s1 + beta[32 + lane], 0.f);
}

// ------------------------------------------------------------------
// pred head: out = h @ predW + predB   [N,64] @ [64,40]
// ------------------------------------------------------------------
__global__ void pred_k(const float* __restrict__ Wp,
                       const float* __restrict__ bp,
                       float* __restrict__ out) {
    __shared__ float Ws[HID * OUT_F];
    __shared__ float bs[OUT_F];
    int tid = threadIdx.x;
    for (int idx = tid; idx < HID * OUT_F; idx += 256) Ws[idx] = Wp[idx];
    if (tid < OUT_F) bs[tid] = bp[tid];
    __syncthreads();
    if (tid >= 240) return;

    int col  = tid % OUT_F;
    int grp  = tid / OUT_F;     // 0..5
    int row0 = blockIdx.x * 24 + grp * 4;
    int r[4];
#pragma unroll
    for (int rr = 0; rr < 4; rr++) r[rr] = min(row0 + rr, NN - 1);

    float acc[4] = {};
#pragma unroll 4
    for (int k = 0; k < HID; k++) {
        float w = Ws[k * OUT_F + col];
#pragma unroll
        for (int rr = 0; rr < 4; rr++)
            acc[rr] += g_h[r[rr] * HID + k] * w;
    }
#pragma unroll
    for (int rr = 0; rr < 4; rr++) {
        int row = row0 + rr;
        if (row < NN) out[row * OUT_F + col] = acc[rr] + bs[col];
    }
}

// ------------------------------------------------------------------
extern "C" void kernel_launch(void* const* d_in, const int* in_sizes, int n_in,
                              void* d_out, int out_size) {
    const float* x     = (const float*)d_in[0];
    const int*   ei    = (const int*)  d_in[1];
    const float* Wf    = (const float*)d_in[2];
    const float* bf    = (const float*)d_in[3];
    const float* convW = (const float*)d_in[4];
    const float* convB = (const float*)d_in[5];
    const float* linW  = (const float*)d_in[6];
    const float* linB  = (const float*)d_in[7];
    const float* gamma = (const float*)d_in[8];
    const float* beta  = (const float*)d_in[9];
    const float* rmean = (const float*)d_in[10];
    const float* rvar  = (const float*)d_in[11];
    const float* predW = (const float*)d_in[12];
    const float* predB = (const float*)d_in[13];
    float* out = (float*)d_out;

    zero_cnt_k <<<(NN + 255) / 256, 256>>>();
    count_deg_k<<<(EE + 255) / 256, 256>>>(ei);
    dinv_k     <<<(NN + 255) / 256, 256>>>();
    scan_k     <<<1, 1024>>>();
    fill_k     <<<(EE + 255) / 256, 256>>>(ei);

    former1_k<<<(NN + 63) / 64, dim3(16, 16)>>>(x, Wf, bf);

    for (int l = 0; l < NLAYER; l++) {
        layer_gemm_k<<<(NN + 31) / 32, dim3(32, 8)>>>(
            convW + l * HID * HID, convB + l * HID,
            linW  + l * HID * HID, linB  + l * HID);
        agg_k<<<(NN + 7) / 8, 256>>>(
            gamma + l * HID, beta + l * HID,
            rmean + l * HID, rvar + l * HID);
    }

    pred_k<<<(NN + 23) / 24, 256>>>(predW, predB, out);
}

// round 2
// speedup vs baseline: 1.2162x; 1.2162x over previous
#include <cuda_runtime.h>

#define NN 50000
#define EE 800000
#define IN_F 128
#define HID 64
#define OUT_F 40
#define NLAYER 3

// ---- scratch (device globals: no allocation allowed) ----
__device__ float g_h[NN * HID];
__device__ float g_hw[NN * HID];
__device__ float g_r[NN * HID];
__device__ float g_dinv[NN];
__device__ int   g_cnt[NN];
__device__ int   g_start[NN];
__device__ int   g_fill[NN];
__device__ int   g_srcbuf[EE];
__device__ int   g_total;

// ------------------------------------------------------------------
// CSR build (unordered segments: starts assigned by atomic bump)
// ------------------------------------------------------------------
__global__ void zero_cnt_k() {
    int i = blockIdx.x * 256 + threadIdx.x;
    if (i < NN) g_cnt[i] = 0;
    if (i == 0) g_total = 0;
}

__global__ void count_deg_k(const int* __restrict__ ei) {
    int e = blockIdx.x * 256 + threadIdx.x;
    if (e < EE) atomicAdd(&g_cnt[ei[EE + e]], 1);
}

// per-node: dinv + segment start via atomic bump (order irrelevant)
__global__ void start_k() {
    int i = blockIdx.x * 256 + threadIdx.x;
    if (i < NN) {
        int c = g_cnt[i];
        g_dinv[i] = rsqrtf((float)c + 1.0f);
        int s = atomicAdd(&g_total, c);
        g_start[i] = s;
        g_fill[i]  = s;
    }
}

__global__ void fill_k(const int* __restrict__ ei) {
    int e = blockIdx.x * 256 + threadIdx.x;
    if (e < EE) {
        int s = ei[e];
        int d = ei[EE + e];
        int pos = atomicAdd(&g_fill[d], 1);
        g_srcbuf[pos] = s;
    }
}

// ------------------------------------------------------------------
// former1: h = x @ Wf + bf     [N,128] @ [128,64]
// blockDim (16,16): 64 cols in 4-col groups, 64 rows/block (4 rows/thread)
// ------------------------------------------------------------------
__global__ void former1_k(const float* __restrict__ x,
                          const float* __restrict__ Wf,
                          const float* __restrict__ bf) {
    __shared__ float Ws[IN_F][HID];
    __shared__ float bs[HID];
    int tid = threadIdx.y * 16 + threadIdx.x;
    for (int idx = tid; idx < IN_F * HID; idx += 256)
        Ws[idx >> 6][idx & 63] = Wf[idx];
    if (tid < HID) bs[tid] = bf[tid];
    __syncthreads();

    int c0   = threadIdx.x * 4;
    int row0 = blockIdx.x * 64 + threadIdx.y * 4;
    int r[4];
#pragma unroll
    for (int rr = 0; rr < 4; rr++) r[rr] = min(row0 + rr, NN - 1);

    float acc[4][4] = {};
#pragma unroll 4
    for (int k = 0; k < IN_F; k++) {
        float4 w = *(const float4*)&Ws[k][c0];
#pragma unroll
        for (int rr = 0; rr < 4; rr++) {
            float xv = __ldg(&x[r[rr] * IN_F + k]);
            acc[rr][0] += xv * w.x;
            acc[rr][1] += xv * w.y;
            acc[rr][2] += xv * w.z;
            acc[rr][3] += xv * w.w;
        }
    }
#pragma unroll
    for (int rr = 0; rr < 4; rr++) {
        int row = row0 + rr;
        if (row < NN) {
            float4 v = make_float4(acc[rr][0] + bs[c0],
                                   acc[rr][1] + bs[c0 + 1],
                                   acc[rr][2] + bs[c0 + 2],
                                   acc[rr][3] + bs[c0 + 3]);
            *(float4*)&g_h[row * HID + c0] = v;
        }
    }
}

// ------------------------------------------------------------------
// per-layer fused GEMM pair: hw = h@convW ; r = h@linW + linB + convB
// blockDim (32,8): 128 combined cols in 4-col groups, 32 rows/block
// ------------------------------------------------------------------
__global__ void layer_gemm_k(const float* __restrict__ convW,
                             const float* __restrict__ convB,
                             const float* __restrict__ linW,
                             const float* __restrict__ linB) {
    __shared__ float Ws[HID][128];
    __shared__ float bs[HID];
    int tid = threadIdx.y * 32 + threadIdx.x;
    for (int idx = tid; idx < HID * 128; idx += 256) {
        int k = idx >> 7, j = idx & 127;
        Ws[k][j] = (j < 64) ? convW[k * 64 + j] : linW[k * 64 + j - 64];
    }
    if (tid < HID) bs[tid] = convB[tid] + linB[tid];
    __syncthreads();

    int c0   = threadIdx.x * 4;                 // combined col [0,128)
    int row0 = blockIdx.x * 32 + threadIdx.y * 4;
    int r[4];
#pragma unroll
    for (int rr = 0; rr < 4; rr++) r[rr] = min(row0 + rr, NN - 1);

    float acc[4][4] = {};
#pragma unroll 4
    for (int k = 0; k < HID; k++) {
        float4 w = *(const float4*)&Ws[k][c0];
#pragma unroll
        for (int rr = 0; rr < 4; rr++) {
            float xv = g_h[r[rr] * HID + k];
            acc[rr][0] += xv * w.x;
            acc[rr][1] += xv * w.y;
            acc[rr][2] += xv * w.z;
            acc[rr][3] += xv * w.w;
        }
    }
    bool isR = (c0 >= 64);
    int  cc  = isR ? (c0 - 64) : c0;
#pragma unroll
    for (int rr = 0; rr < 4; rr++) {
        int row = row0 + rr;
        if (row < NN) {
            float4 v = make_float4(acc[rr][0], acc[rr][1], acc[rr][2], acc[rr][3]);
            if (isR) {
                v.x += bs[cc]; v.y += bs[cc + 1];
                v.z += bs[cc + 2]; v.w += bs[cc + 3];
                *(float4*)&g_r[row * HID + cc] = v;
            } else {
                *(float4*)&g_hw[row * HID + cc] = v;
            }
        }
    }
}

// ------------------------------------------------------------------
// aggregation + self loop + residual + BN(eval) + ReLU  (warp per node)
// ------------------------------------------------------------------
__global__ void agg_k(const float* __restrict__ gamma,
                      const float* __restrict__ beta,
                      const float* __restrict__ mean,
                      const float* __restrict__ var) {
    int warp = threadIdx.x >> 5;
    int lane = threadIdx.x & 31;
    int node = blockIdx.x * 8 + warp;
    if (node >= NN) return;

    float dn   = g_dinv[node];
    float self = dn * dn;
    int beg = g_start[node];
    int end = beg + g_cnt[node];

    float a0 = g_hw[node * 64 + lane] * self;
    float a1 = g_hw[node * 64 + 32 + lane] * self;
    for (int i = beg; i < end; i++) {
        int   s = __ldg(&g_srcbuf[i]);
        float c = __ldg(&g_dinv[s]) * dn;
        a0 += c * __ldg(&g_hw[s * 64 + lane]);
        a1 += c * __ldg(&g_hw[s * 64 + 32 + lane]);
    }
    a0 += g_r[node * 64 + lane];
    a1 += g_r[node * 64 + 32 + lane];

    float s0 = gamma[lane]      * rsqrtf(var[lane]      + 1e-5f);
    float s1 = gamma[32 + lane] * rsqrtf(var[32 + lane] + 1e-5f);
    g_h[node * 64 + lane]      = fmaxf((a0 - mean[lane])      * s0 + beta[lane],      0.f);
    g_h[node * 64 + 32 + lane] = fmaxf((a1 - mean[32 + lane]) * s1 + beta[32 + lane], 0.f);
}

// ------------------------------------------------------------------
// pred head: out = h @ predW + predB   [N,64] @ [64,40]
// ------------------------------------------------------------------
__global__ void pred_k(const float* __restrict__ Wp,
                       const float* __restrict__ bp,
                       float* __restrict__ out) {
    __shared__ float Ws[HID * OUT_F];
    __shared__ float bs[OUT_F];
    int tid = threadIdx.x;
    for (int idx = tid; idx < HID * OUT_F; idx += 256) Ws[idx] = Wp[idx];
    if (tid < OUT_F) bs[tid] = bp[tid];
    __syncthreads();
    if (tid >= 240) return;

    int col  = tid % OUT_F;
    int grp  = tid / OUT_F;     // 0..5
    int row0 = blockIdx.x * 24 + grp * 4;
    int r[4];
#pragma unroll
    for (int rr = 0; rr < 4; rr++) r[rr] = min(row0 + rr, NN - 1);

    float acc[4] = {};
#pragma unroll 4
    for (int k = 0; k < HID; k++) {
        float w = Ws[k * OUT_F + col];
#pragma unroll
        for (int rr = 0; rr < 4; rr++)
            acc[rr] += g_h[r[rr] * HID + k] * w;
    }
#pragma unroll
    for (int rr = 0; rr < 4; rr++) {
        int row = row0 + rr;
        if (row < NN) out[row * OUT_F + col] = acc[rr] + bs[col];
    }
}

// ------------------------------------------------------------------
extern "C" void kernel_launch(void* const* d_in, const int* in_sizes, int n_in,
                              void* d_out, int out_size) {
    const float* x     = (const float*)d_in[0];
    const int*   ei    = (const int*)  d_in[1];
    const float* Wf    = (const float*)d_in[2];
    const float* bf    = (const float*)d_in[3];
    const float* convW = (const float*)d_in[4];
    const float* convB = (const float*)d_in[5];
    const float* linW  = (const float*)d_in[6];
    const float* linB  = (const float*)d_in[7];
    const float* gamma = (const float*)d_in[8];
    const float* beta  = (const float*)d_in[9];
    const float* rmean = (const float*)d_in[10];
    const float* rvar  = (const float*)d_in[11];
    const float* predW = (const float*)d_in[12];
    const float* predB = (const float*)d_in[13];
    float* out = (float*)d_out;

    zero_cnt_k <<<(NN + 255) / 256, 256>>>();
    count_deg_k<<<(EE + 255) / 256, 256>>>(ei);
    start_k    <<<(NN + 255) / 256, 256>>>();
    fill_k     <<<(EE + 255) / 256, 256>>>(ei);

    former1_k<<<(NN + 63) / 64, dim3(16, 16)>>>(x, Wf, bf);

    for (int l = 0; l < NLAYER; l++) {
        layer_gemm_k<<<(NN + 31) / 32, dim3(32, 8)>>>(
            convW + l * HID * HID, convB + l * HID,
            linW  + l * HID * HID, linB  + l * HID);
        agg_k<<<(NN + 7) / 8, 256>>>(
            gamma + l * HID, beta + l * HID,
            rmean + l * HID, rvar + l * HID);
    }

    pred_k<<<(NN + 23) / 24, 256>>>(predW, predB, out);
}

// round 4
// speedup vs baseline: 1.4575x; 1.1983x over previous
#include <cuda_runtime.h>

#define NN 50000
#define EE 800000
#define IN_F 128
#define HID 64
#define OUT_F 40
#define NLAYER 3

// ---- scratch (device globals: no allocation allowed) ----
__device__ float g_h[NN * HID];     // layer activations
__device__ float g_hws[NN * HID];   // dinv-prescaled conv GEMM output
__device__ float g_r[NN * HID];     // residual path output
__device__ float g_dinv[NN];
__device__ int   g_cnt[NN];
__device__ int   g_start[NN];
__device__ int   g_fill[NN];
__device__ int   g_srcbuf[EE];
__device__ int   g_total;

// ------------------------------------------------------------------
// CSR build (unordered segments: starts assigned by atomic bump)
// ------------------------------------------------------------------
__global__ void zero_cnt_k() {
    int i = blockIdx.x * 256 + threadIdx.x;
    if (i < NN) g_cnt[i] = 0;
    if (i == 0) g_total = 0;
}

__global__ void count_deg_k(const int* __restrict__ ei) {
    int e = blockIdx.x * 256 + threadIdx.x;
    if (e < EE) atomicAdd(&g_cnt[ei[EE + e]], 1);
}

__global__ void start_k() {
    int i = blockIdx.x * 256 + threadIdx.x;
    if (i < NN) {
        int c = g_cnt[i];
        g_dinv[i] = rsqrtf((float)c + 1.0f);
        int s = atomicAdd(&g_total, c);
        g_start[i] = s;
        g_fill[i]  = s;
    }
}

__global__ void fill_k(const int* __restrict__ ei) {
    int e = blockIdx.x * 256 + threadIdx.x;
    if (e < EE) {
        int s = ei[e];
        int d = ei[EE + e];
        int pos = atomicAdd(&g_fill[d], 1);
        g_srcbuf[pos] = s;
    }
}

// ------------------------------------------------------------------
// former1: h = x @ Wf + bf     [N,128] @ [128,64]
// blockDim (16,16): 64 cols in 4-col groups, 64 rows/block, k in groups of 4
// ------------------------------------------------------------------
__global__ void former1_k(const float* __restrict__ x,
                          const float* __restrict__ Wf,
                          const float* __restrict__ bf) {
    __shared__ float Ws[IN_F][HID];
    __shared__ float bs[HID];
    int tid = threadIdx.y * 16 + threadIdx.x;
    for (int idx = tid; idx < IN_F * HID; idx += 256)
        Ws[idx >> 6][idx & 63] = Wf[idx];
    if (tid < HID) bs[tid] = bf[tid];
    __syncthreads();

    int c0   = threadIdx.x * 4;
    int row0 = blockIdx.x * 64 + threadIdx.y * 4;
    int r[4];
#pragma unroll
    for (int rr = 0; rr < 4; rr++) r[rr] = min(row0 + rr, NN - 1);

    float acc[4][4] = {};
    for (int k = 0; k < IN_F; k += 4) {
        float4 xv[4];
#pragma unroll
        for (int rr = 0; rr < 4; rr++)
            xv[rr] = *(const float4*)&x[r[rr] * IN_F + k];
#pragma unroll
        for (int kk = 0; kk < 4; kk++) {
            float4 w = *(const float4*)&Ws[k + kk][c0];
#pragma unroll
            for (int rr = 0; rr < 4; rr++) {
                float xs = (kk == 0) ? xv[rr].x : (kk == 1) ? xv[rr].y
                         : (kk == 2) ? xv[rr].z : xv[rr].w;
                acc[rr][0] += xs * w.x;
                acc[rr][1] += xs * w.y;
                acc[rr][2] += xs * w.z;
                acc[rr][3] += xs * w.w;
            }
        }
    }
#pragma unroll
    for (int rr = 0; rr < 4; rr++) {
        int row = row0 + rr;
        if (row < NN) {
            float4 v = make_float4(acc[rr][0] + bs[c0],
                                   acc[rr][1] + bs[c0 + 1],
                                   acc[rr][2] + bs[c0 + 2],
                                   acc[rr][3] + bs[c0 + 3]);
            *(float4*)&g_h[row * HID + c0] = v;
        }
    }
}

// ------------------------------------------------------------------
// per-layer fused GEMM pair:
//   hws = dinv[row] * (h @ convW)          (prescaled for aggregation)
//   r   = h @ linW + linB + convB
// blockDim (32,8): 128 combined cols in 4-col groups, 32 rows/block
// ------------------------------------------------------------------
__global__ void layer_gemm_k(const float* __restrict__ convW,
                             const float* __restrict__ convB,
                             const float* __restrict__ linW,
                             const float* __restrict__ linB) {
    __shared__ float Ws[HID][128];
    __shared__ float bs[HID];
    int tid = threadIdx.y * 32 + threadIdx.x;
    for (int idx = tid; idx < HID * 128; idx += 256) {
        int k = idx >> 7, j = idx & 127;
        Ws[k][j] = (j < 64) ? convW[k * 64 + j] : linW[k * 64 + j - 64];
    }
    if (tid < HID) bs[tid] = convB[tid] + linB[tid];
    __syncthreads();

    int c0   = threadIdx.x * 4;                 // combined col [0,128)
    int row0 = blockIdx.x * 32 + threadIdx.y * 4;
    int r[4];
#pragma unroll
    for (int rr = 0; rr < 4; rr++) r[rr] = min(row0 + rr, NN - 1);

    float acc[4][4] = {};
    for (int k = 0; k < HID; k += 4) {
        float4 xv[4];
#pragma unroll
        for (int rr = 0; rr < 4; rr++)
            xv[rr] = *(const float4*)&g_h[r[rr] * HID + k];
#pragma unroll
        for (int kk = 0; kk < 4; kk++) {
            float4 w = *(const float4*)&Ws[k + kk][c0];
#pragma unroll
            for (int rr = 0; rr < 4; rr++) {
                float xs = (kk == 0) ? xv[rr].x : (kk == 1) ? xv[rr].y
                         : (kk == 2) ? xv[rr].z : xv[rr].w;
                acc[rr][0] += xs * w.x;
                acc[rr][1] += xs * w.y;
                acc[rr][2] += xs * w.z;
                acc[rr][3] += xs * w.w;
            }
        }
    }
    bool isR = (c0 >= 64);
    int  cc  = isR ? (c0 - 64) : c0;
#pragma unroll
    for (int rr = 0; rr < 4; rr++) {
        int row = row0 + rr;
        if (row < NN) {
            float4 v = make_float4(acc[rr][0], acc[rr][1], acc[rr][2], acc[rr][3]);
            if (isR) {
                v.x += bs[cc]; v.y += bs[cc + 1];
                v.z += bs[cc + 2]; v.w += bs[cc + 3];
                *(float4*)&g_r[row * HID + cc] = v;
            } else {
                float dv = g_dinv[row];
                v.x *= dv; v.y *= dv; v.z *= dv; v.w *= dv;
                *(float4*)&g_hws[row * HID + cc] = v;
            }
        }
    }
}

// ------------------------------------------------------------------
// aggregation: h = relu(BN( dn*(sum_e hws[src] + hws[node]) + r[node] ))
// warp per node, float2 per lane (pure gather-add edge loop)
// ------------------------------------------------------------------
__global__ void agg_k(const float* __restrict__ gamma,
                      const float* __restrict__ beta,
                      const float* __restrict__ mean,
                      const float* __restrict__ var) {
    int warp = threadIdx.x >> 5;
    int lane = threadIdx.x & 31;
    int node = blockIdx.x * 8 + warp;
    if (node >= NN) return;

    int c = lane * 2;                       // this lane's 2 columns
    float dn  = g_dinv[node];
    int   beg = g_start[node];
    int   end = beg + g_cnt[node];

    const float2* hws = (const float2*)g_hws;
    float2 a = hws[node * 32 + lane];       // self term (already dinv-scaled)

    int i = beg;
    for (; i + 4 <= end; i += 4) {
        int s0 = __ldg(&g_srcbuf[i]);
        int s1 = __ldg(&g_srcbuf[i + 1]);
        int s2 = __ldg(&g_srcbuf[i + 2]);
        int s3 = __ldg(&g_srcbuf[i + 3]);
        float2 v0 = __ldg(&hws[s0 * 32 + lane]);
        float2 v1 = __ldg(&hws[s1 * 32 + lane]);
        float2 v2 = __ldg(&hws[s2 * 32 + lane]);
        float2 v3 = __ldg(&hws[s3 * 32 + lane]);
        a.x += v0.x + v1.x + v2.x + v3.x;
        a.y += v0.y + v1.y + v2.y + v3.y;
    }
    for (; i < end; i++) {
        int s = __ldg(&g_srcbuf[i]);
        float2 v = __ldg(&hws[s * 32 + lane]);
        a.x += v.x;
        a.y += v.y;
    }

    float2 rr = ((const float2*)g_r)[node * 32 + lane];
    a.x = a.x * dn + rr.x;
    a.y = a.y * dn + rr.y;

    float s0 = gamma[c]     * rsqrtf(var[c]     + 1e-5f);
    float s1 = gamma[c + 1] * rsqrtf(var[c + 1] + 1e-5f);
    float2 o;
    o.x = fmaxf((a.x - mean[c])     * s0 + beta[c],     0.f);
    o.y = fmaxf((a.y - mean[c + 1]) * s1 + beta[c + 1], 0.f);
    ((float2*)g_h)[node * 32 + lane] = o;
}

// ------------------------------------------------------------------
// pred head: out = h @ predW + predB   [N,64] @ [64,40]
// ------------------------------------------------------------------
__global__ void pred_k(const float* __restrict__ Wp,
                       const float* __restrict__ bp,
                       float* __restrict__ out) {
    __shared__ float Ws[HID * OUT_F];
    __shared__ float bs[OUT_F];
    int tid = threadIdx.x;
    for (int idx = tid; idx < HID * OUT_F; idx += 256) Ws[idx] = Wp[idx];
    if (tid < OUT_F) bs[tid] = bp[tid];
    __syncthreads();
    if (tid >= 240) return;

    int col  = tid % OUT_F;
    int grp  = tid / OUT_F;     // 0..5
    int row0 = blockIdx.x * 24 + grp * 4;
    int r[4];
#pragma unroll
    for (int rr = 0; rr < 4; rr++) r[rr] = min(row0 + rr, NN - 1);

    float acc[4] = {};
    for (int k = 0; k < HID; k += 4) {
        float4 hv[4];
#pragma unroll
        for (int rr = 0; rr < 4; rr++)
            hv[rr] = *(const float4*)&g_h[r[rr] * HID + k];
#pragma unroll
        for (int kk = 0; kk < 4; kk++) {
            float w = Ws[(k + kk) * OUT_F + col];
#pragma unroll
            for (int rr = 0; rr < 4; rr++) {
                float xs = (kk == 0) ? hv[rr].x : (kk == 1) ? hv[rr].y
                         : (kk == 2) ? hv[rr].z : hv[rr].w;
                acc[rr] += xs * w;
            }
        }
    }
#pragma unroll
    for (int rr = 0; rr < 4; rr++) {
        int row = row0 + rr;
        if (row < NN) out[row * OUT_F + col] = acc[rr] + bs[col];
    }
}

// ------------------------------------------------------------------
extern "C" void kernel_launch(void* const* d_in, const int* in_sizes, int n_in,
                              void* d_out, int out_size) {
    const float* x     = (const float*)d_in[0];
    const int*   ei    = (const int*)  d_in[1];
    const float* Wf    = (const float*)d_in[2];
    const float* bf    = (const float*)d_in[3];
    const float* convW = (const float*)d_in[4];
    const float* convB = (const float*)d_in[5];
    const float* linW  = (const float*)d_in[6];
    const float* linB  = (const float*)d_in[7];
    const float* gamma = (const float*)d_in[8];
    const float* beta  = (const float*)d_in[9];
    const float* rmean = (const float*)d_in[10];
    const float* rvar  = (const float*)d_in[11];
    const float* predW = (const float*)d_in[12];
    const float* predB = (const float*)d_in[13];
    float* out = (float*)d_out;

    zero_cnt_k <<<(NN + 255) / 256, 256>>>();
    count_deg_k<<<(EE + 255) / 256, 256>>>(ei);
    start_k    <<<(NN + 255) / 256, 256>>>();
    fill_k     <<<(EE + 255) / 256, 256>>>(ei);

    former1_k<<<(NN + 63) / 64, dim3(16, 16)>>>(x, Wf, bf);

    for (int l = 0; l < NLAYER; l++) {
        layer_gemm_k<<<(NN + 31) / 32, dim3(32, 8)>>>(
            convW + l * HID * HID, convB + l * HID,
            linW  + l * HID * HID, linB  + l * HID);
        agg_k<<<(NN + 7) / 8, 256>>>(
            gamma + l * HID, beta + l * HID,
            rmean + l * HID, rvar + l * HID);
    }

    pred_k<<<(NN + 23) / 24, 256>>>(predW, predB, out);
}